// round 2
// baseline (speedup 1.0000x reference)
#include <cuda_runtime.h>

#define DD  1024
#define BB  128
#define LLn 196
#define LP1 197
#define NLUT 1024
#define LUT_SCALE 102.4f      // NLUT / 10  (range [-5,5])
#define LUT_CENTER 512.0f

// ---------------- scratch (no allocs allowed) ----------------
__device__ float g_fr [BB*DD];
__device__ float g_fre[BB*DD];
__device__ float g_ho [BB*DD];
__device__ float g_hoe[BB*DD];
__device__ float g_att[BB*DD];
__device__ float g_scores[BB*LP1];
__device__ float g_pi[BB*LP1];
__device__ float2 g_lut[NLUT];

// ---------------- f32x2 helpers ----------------
__device__ __forceinline__ unsigned long long fma2(unsigned long long a,
                                                   unsigned long long b,
                                                   unsigned long long c) {
    unsigned long long r;
    asm("fma.rn.f32x2 %0, %1, %2, %3;" : "=l"(r) : "l"(a), "l"(b), "l"(c));
    return r;
}
__device__ __forceinline__ unsigned long long dup2(float x) {
    unsigned long long r;
    asm("mov.b64 %0, {%1, %1};" : "=l"(r) : "f"(x));
    return r;
}

// ---------------- LUT init (runs every call; deterministic) ----------------
__global__ void lut_init_kernel()
{
    int i = threadIdx.x;            // 1 block, NLUT threads
    float x0 = -5.0f + 10.0f * (float)i / (float)NLUT;
    float x1 = -5.0f + 10.0f * (float)(i + 1) / (float)NLUT;
    float t0 = tanhf(x0), t1 = tanhf(x1);
    g_lut[i] = make_float2(t0, t1 - t0);
}

// ---------------- GEMM: C[128,1024] = act(A @ W^T + b) ----------------
// BM=32, BN=64, BK=16, 128 threads, thread tile 4m x 4n (m-paired f32x2 accum).
// B tile stored pre-duplicated as u64 to avoid per-k dup movs.
__global__ void __launch_bounds__(128)
gemm_kernel(const float* __restrict__ A0, const float* __restrict__ W0,
            const float* __restrict__ bias0, float* __restrict__ C0, int act0,
            const float* __restrict__ A1, const float* __restrict__ W1,
            const float* __restrict__ bias1, float* __restrict__ C1, int act1)
{
    const float* A  = A0;  const float* W = W0;  const float* bias = bias0;
    float* C = C0;  int act = act0;
    if (blockIdx.z == 1) { A = A1; W = W1; bias = bias1; C = C1; act = act1; }

    __shared__ float As[2][16][32];
    __shared__ unsigned long long Bs[2][16][64];   // duplicated pairs

    const int t  = threadIdx.x;
    const int bm = blockIdx.y << 5;
    const int bn = blockIdx.x << 6;

    const int ar = t >> 2, ac = (t & 3) << 2;   // A loader: row 0..31, k 0/4/8/12
    const int br = t >> 1, bc = (t & 1) << 3;   // W loader: row 0..63, k 0/8
    const int tx = t & 15, ty = t >> 4;
    const int m0 = ty << 2, n0 = tx << 2;

    const float* Ap = A + (size_t)(bm + ar) * DD + ac;
    const float* Wp = W + (size_t)(bn + br) * DD + bc;

    unsigned long long acc01[4], acc23[4];
#pragma unroll
    for (int j = 0; j < 4; j++) { acc01[j] = 0ull; acc23[j] = 0ull; }

    float4 av  = *(const float4*)Ap;
    float4 bv0 = *(const float4*)Wp;
    float4 bv1 = *(const float4*)(Wp + 4);

    As[0][ac+0][ar] = av.x;  As[0][ac+1][ar] = av.y;
    As[0][ac+2][ar] = av.z;  As[0][ac+3][ar] = av.w;
    Bs[0][bc+0][br] = dup2(bv0.x); Bs[0][bc+1][br] = dup2(bv0.y);
    Bs[0][bc+2][br] = dup2(bv0.z); Bs[0][bc+3][br] = dup2(bv0.w);
    Bs[0][bc+4][br] = dup2(bv1.x); Bs[0][bc+5][br] = dup2(bv1.y);
    Bs[0][bc+6][br] = dup2(bv1.z); Bs[0][bc+7][br] = dup2(bv1.w);
    __syncthreads();

    int buf = 0;
#pragma unroll 1
    for (int kb = 0; kb < 64; kb++) {
        if (kb < 63) {
            av  = *(const float4*)(Ap + (kb + 1) * 16);
            bv0 = *(const float4*)(Wp + (kb + 1) * 16);
            bv1 = *(const float4*)(Wp + (kb + 1) * 16 + 4);
        }
#pragma unroll
        for (int k = 0; k < 16; k++) {
            union { float4 v; unsigned long long u[2]; } au;
            au.v = *(const float4*)&As[buf][k][m0];
            union { ulonglong2 v; unsigned long long u[2]; } b01, b23;
            b01.v = *(const ulonglong2*)&Bs[buf][k][n0];
            b23.v = *(const ulonglong2*)&Bs[buf][k][n0 + 2];
            acc01[0] = fma2(au.u[0], b01.u[0], acc01[0]);
            acc01[1] = fma2(au.u[0], b01.u[1], acc01[1]);
            acc01[2] = fma2(au.u[0], b23.u[0], acc01[2]);
            acc01[3] = fma2(au.u[0], b23.u[1], acc01[3]);
            acc23[0] = fma2(au.u[1], b01.u[0], acc23[0]);
            acc23[1] = fma2(au.u[1], b01.u[1], acc23[1]);
            acc23[2] = fma2(au.u[1], b23.u[0], acc23[2]);
            acc23[3] = fma2(au.u[1], b23.u[1], acc23[3]);
        }
        if (kb < 63) {
            const int nb = buf ^ 1;
            As[nb][ac+0][ar] = av.x;  As[nb][ac+1][ar] = av.y;
            As[nb][ac+2][ar] = av.z;  As[nb][ac+3][ar] = av.w;
            Bs[nb][bc+0][br] = dup2(bv0.x); Bs[nb][bc+1][br] = dup2(bv0.y);
            Bs[nb][bc+2][br] = dup2(bv0.z); Bs[nb][bc+3][br] = dup2(bv0.w);
            Bs[nb][bc+4][br] = dup2(bv1.x); Bs[nb][bc+5][br] = dup2(bv1.y);
            Bs[nb][bc+6][br] = dup2(bv1.z); Bs[nb][bc+7][br] = dup2(bv1.w);
            __syncthreads();
            buf = nb;
        }
    }

    const float4 bi = *(const float4*)&bias[bn + n0];
    const float bif[4] = { bi.x, bi.y, bi.z, bi.w };
#pragma unroll
    for (int i = 0; i < 4; i++) {
        float o[4];
#pragma unroll
        for (int j = 0; j < 4; j++) {
            union { unsigned long long u; float f[2]; } u;
            u.u = (i < 2) ? acc01[j] : acc23[j];
            o[j] = u.f[i & 1] + bif[j];
        }
        if (act == 1) {
#pragma unroll
            for (int j = 0; j < 4; j++) o[j] = fmaxf(o[j], 0.0f);
        } else if (act == 2) {
#pragma unroll
            for (int j = 0; j < 4; j++) o[j] = tanhf(o[j]);
        }
        float4 ov; ov.x = o[0]; ov.y = o[1]; ov.z = o[2]; ov.w = o[3];
        *(float4*)&C[(size_t)(bm + m0 + i) * DD + bn + n0] = ov;
    }
}

// ---------------- scores[b,l] = Wa . tanh(E[b,l,:] + hoe[b,:]) + ba ----------------
// LUT-based tanh (no MUFU). One warp per l; 512 threads; grid (13, 128).
__global__ void __launch_bounds__(512)
scores_kernel(const float* __restrict__ embed,
              const float* __restrict__ Wa, const float* __restrict__ ba)
{
    __shared__ float2 slut[NLUT];  // 8KB

    const int t = threadIdx.x;
    // copy LUT to shared (512 threads x 2 entries = 16B per thread)
    {
        const float4* src = (const float4*)g_lut;
        float4* dst = (float4*)slut;
        dst[t] = src[t];
    }

    const int b    = blockIdx.y;
    const int w    = t >> 5;
    const int lane = t & 31;
    const int l    = blockIdx.x * 16 + w;

    // preload hb (= hoe*scale + center) and wa for this lane's 32 d-indices
    float hb[32], wa[32];
    const float* hrow = g_hoe + (size_t)b * DD;
#pragma unroll
    for (int p = 0; p < 4; p++) {
        const int d = p * 256 + lane * 8;
        float4 h0 = *(const float4*)(hrow + d);
        float4 h1 = *(const float4*)(hrow + d + 4);
        float4 w0 = *(const float4*)(Wa + d);
        float4 w1 = *(const float4*)(Wa + d + 4);
        hb[p*8+0] = fmaf(h0.x, LUT_SCALE, LUT_CENTER);
        hb[p*8+1] = fmaf(h0.y, LUT_SCALE, LUT_CENTER);
        hb[p*8+2] = fmaf(h0.z, LUT_SCALE, LUT_CENTER);
        hb[p*8+3] = fmaf(h0.w, LUT_SCALE, LUT_CENTER);
        hb[p*8+4] = fmaf(h1.x, LUT_SCALE, LUT_CENTER);
        hb[p*8+5] = fmaf(h1.y, LUT_SCALE, LUT_CENTER);
        hb[p*8+6] = fmaf(h1.z, LUT_SCALE, LUT_CENTER);
        hb[p*8+7] = fmaf(h1.w, LUT_SCALE, LUT_CENTER);
        wa[p*8+0] = w0.x; wa[p*8+1] = w0.y; wa[p*8+2] = w0.z; wa[p*8+3] = w0.w;
        wa[p*8+4] = w1.x; wa[p*8+5] = w1.y; wa[p*8+6] = w1.z; wa[p*8+7] = w1.w;
    }
    __syncthreads();

    if (l >= LP1) return;

    const float* row = (l == 0) ? (g_fre + (size_t)b * DD)
                                : (embed + ((size_t)b * LLn + (l - 1)) * DD);
    float acc = 0.0f;
#pragma unroll
    for (int p = 0; p < 4; p++) {
        const int d = p * 256 + lane * 8;
        float4 e0 = *(const float4*)(row + d);
        float4 e1 = *(const float4*)(row + d + 4);
        float ev[8] = { e0.x, e0.y, e0.z, e0.w, e1.x, e1.y, e1.z, e1.w };
#pragma unroll
        for (int j = 0; j < 8; j++) {
            float tt = fmaf(ev[j], LUT_SCALE, hb[p*8+j]);
            tt = fminf(fmaxf(tt, 0.0f), 1023.9999f);
            int   i  = (int)tt;
            float fr = tt - (float)i;
            float2 c = slut[i];
            float y  = fmaf(c.y, fr, c.x);
            acc = fmaf(y, wa[p*8+j], acc);
        }
    }
#pragma unroll
    for (int o = 16; o; o >>= 1) acc += __shfl_xor_sync(0xffffffffu, acc, o);
    if (lane == 0) g_scores[b * LP1 + l] = acc + ba[0];
}

// ---------------- softmax over L+1=197 per batch row ----------------
__global__ void __launch_bounds__(256)
softmax_kernel()
{
    const int b = blockIdx.x, t = threadIdx.x;
    __shared__ float red[8];

    float v = (t < LP1) ? g_scores[b * LP1 + t] : -3.4e38f;
    float m = v;
#pragma unroll
    for (int o = 16; o; o >>= 1) m = fmaxf(m, __shfl_xor_sync(0xffffffffu, m, o));
    if ((t & 31) == 0) red[t >> 5] = m;
    __syncthreads();
    float mx = red[0];
#pragma unroll
    for (int i = 1; i < 8; i++) mx = fmaxf(mx, red[i]);
    __syncthreads();

    float e = (t < LP1) ? expf(v - mx) : 0.0f;
    float s = e;
#pragma unroll
    for (int o = 16; o; o >>= 1) s += __shfl_xor_sync(0xffffffffu, s, o);
    if ((t & 31) == 0) red[t >> 5] = s;
    __syncthreads();
    float tot = red[0] + red[1] + red[2] + red[3]
              + red[4] + red[5] + red[6] + red[7];
    if (t < LP1) g_pi[b * LP1 + t] = e / tot;
}

// ---------------- att[b,:] = PI[b,0]*fr + sum_l PI[b,l+1]*conv[b,l,:] + ho[b,:] ----------------
__global__ void __launch_bounds__(256)
wsum_kernel(const float* __restrict__ conv)
{
    const int b = blockIdx.x, t = threadIdx.x;
    __shared__ float sp[LP1];
    if (t < LP1) sp[t] = g_pi[b * LP1 + t];
    __syncthreads();

    const int d0 = t << 2;
    float4 acc;
    {
        float4 f = *(const float4*)(g_fr + (size_t)b * DD + d0);
        float p = sp[0];
        acc.x = f.x * p; acc.y = f.y * p; acc.z = f.z * p; acc.w = f.w * p;
    }
    const float* base = conv + (size_t)b * LLn * DD + d0;
#pragma unroll 1
    for (int l = 0; l < LLn; l += 4) {
        float4 v0 = *(const float4*)(base + (size_t)(l + 0) * DD);
        float4 v1 = *(const float4*)(base + (size_t)(l + 1) * DD);
        float4 v2 = *(const float4*)(base + (size_t)(l + 2) * DD);
        float4 v3 = *(const float4*)(base + (size_t)(l + 3) * DD);
        float p0 = sp[l + 1], p1 = sp[l + 2], p2 = sp[l + 3], p3 = sp[l + 4];
        acc.x += v0.x * p0; acc.y += v0.y * p0; acc.z += v0.z * p0; acc.w += v0.w * p0;
        acc.x += v1.x * p1; acc.y += v1.y * p1; acc.z += v1.z * p1; acc.w += v1.w * p1;
        acc.x += v2.x * p2; acc.y += v2.y * p2; acc.z += v2.z * p2; acc.w += v2.w * p2;
        acc.x += v3.x * p3; acc.y += v3.y * p3; acc.z += v3.z * p3; acc.w += v3.w * p3;
    }
    float4 h = *(const float4*)(g_ho + (size_t)b * DD + d0);
    acc.x += h.x; acc.y += h.y; acc.z += h.z; acc.w += h.w;
    *(float4*)(g_att + (size_t)b * DD + d0) = acc;
}

// ---------------- host launcher ----------------
extern "C" void kernel_launch(void* const* d_in, const int* in_sizes, int n_in,
                              void* d_out, int out_size)
{
    (void)in_sizes; (void)n_in; (void)out_size;
    const float* h_out = (const float*)d_in[0];
    const float* fake  = (const float*)d_in[1];
    const float* conv  = (const float*)d_in[2];
    const float* embed = (const float*)d_in[3];
    const float* W_fr  = (const float*)d_in[4];
    const float* b_fr  = (const float*)d_in[5];
    const float* W_fre = (const float*)d_in[6];
    const float* b_fre = (const float*)d_in[7];
    const float* W_ho  = (const float*)d_in[8];
    const float* b_ho  = (const float*)d_in[9];
    const float* W_hoe = (const float*)d_in[10];
    const float* b_hoe = (const float*)d_in[11];
    const float* W_a   = (const float*)d_in[12];
    const float* b_a   = (const float*)d_in[13];
    const float* W_h   = (const float*)d_in[14];
    const float* b_h   = (const float*)d_in[15];

    float *fr, *fre, *ho, *hoe, *att;
    cudaGetSymbolAddress((void**)&fr,  g_fr);
    cudaGetSymbolAddress((void**)&fre, g_fre);
    cudaGetSymbolAddress((void**)&ho,  g_ho);
    cudaGetSymbolAddress((void**)&hoe, g_hoe);
    cudaGetSymbolAddress((void**)&att, g_att);

    lut_init_kernel<<<1, NLUT>>>();

    dim3 gb(128);
    // fr = relu(fake @ W_fr^T + b), ho = tanh(h_out @ W_ho^T + b)
    gemm_kernel<<<dim3(16, 4, 2), gb>>>(fake, W_fr, b_fr, fr, 1,
                                        h_out, W_ho, b_ho, ho, 2);
    // fr_e = fr @ W_fre^T + b, ho_e = ho @ W_hoe^T + b
    gemm_kernel<<<dim3(16, 4, 2), gb>>>(fr, W_fre, b_fre, fre, 0,
                                        ho, W_hoe, b_hoe, hoe, 0);
    scores_kernel<<<dim3(13, BB), 512>>>(embed, W_a, b_a);
    softmax_kernel<<<BB, 256>>>();
    wsum_kernel<<<BB, 256>>>(conv);
    // h = tanh(att @ W_h^T + b_h)
    gemm_kernel<<<dim3(16, 4, 1), gb>>>(att, W_h, b_h, (float*)d_out, 2,
                                        att, W_h, b_h, (float*)d_out, 2);
}

// round 6
// speedup vs baseline: 1.7362x; 1.7362x over previous
#include <cuda_runtime.h>

#define DD  1024
#define BB  128
#define LLn 196
#define LP1 197

// ---------------- scratch (no allocs allowed) ----------------
__device__ float g_fr [BB*DD];
__device__ float g_fre[BB*DD];
__device__ float g_ho [BB*DD];
__device__ float g_hoe[BB*DD];
__device__ float g_att[BB*DD];
__device__ float g_scores[BB*LP1];
__device__ float g_part[4][BB*DD];   // GEMM K-split partials

// ---------------- helpers ----------------
__device__ __forceinline__ unsigned long long fma2(unsigned long long a,
                                                   unsigned long long b,
                                                   unsigned long long c) {
    unsigned long long r;
    asm("fma.rn.f32x2 %0, %1, %2, %3;" : "=l"(r) : "l"(a), "l"(b), "l"(c));
    return r;
}
__device__ __forceinline__ unsigned long long dup2(float x) {
    unsigned long long r;
    asm("mov.b64 %0, {%1, %1};" : "=l"(r) : "f"(x));
    return r;
}
__device__ __forceinline__ float tanh_fast(float x) {
    float y;
    asm("tanh.approx.f32 %0, %1;" : "=f"(y) : "f"(x));
    return y;
}

// ---------------- GEMM partial: P = A[.,kh] @ W[.,kh]^T ----------------
// BM=64, BN=64, BK=16, 128 threads, thread tile 4m x 8n (n-paired f32x2 accum).
// grid (16, 2, z): z<2 -> problem 0 (khalf=z), z>=2 -> problem 1 (khalf=z-2).
// Raw partials go to g_part[z]; bias/activation applied by combine_kernel.
__global__ void __launch_bounds__(128)
gemm_kernel(const float* __restrict__ A0, const float* __restrict__ W0,
            const float* __restrict__ A1, const float* __restrict__ W1)
{
    const int bz = blockIdx.z;
    const float* A = (bz < 2) ? A0 : A1;
    const float* W = (bz < 2) ? W0 : W1;
    const int koff = (bz & 1) << 9;           // 0 or 512
    float* P = g_part[bz];

    __shared__ float As[2][16][72];           // padded rows: conflict-free STS
    __shared__ float Bs[2][16][72];

    const int t  = threadIdx.x;
    const int bn = blockIdx.x << 6;
    const int bm = blockIdx.y << 6;

    const int lr = t >> 2;                    // loader row 0..31 (and +32)
    const int lc = (t & 3) << 2;              // loader k col 0/4/8/12
    const float* Ap = A + (size_t)(bm + lr) * DD + koff + lc;
    const float* Wp = W + (size_t)(bn + lr) * DD + koff + lc;

    const int tx = t & 7, ty = t >> 3;
    const int m0 = ty << 2, n0 = tx << 3;

    unsigned long long acc[4][4];
#pragma unroll
    for (int i = 0; i < 4; i++)
#pragma unroll
        for (int j = 0; j < 4; j++) acc[i][j] = 0ull;

    float4 a0 = *(const float4*)Ap;
    float4 a1 = *(const float4*)(Ap + (size_t)32 * DD);
    float4 b0 = *(const float4*)Wp;
    float4 b1 = *(const float4*)(Wp + (size_t)32 * DD);

    {
        float av0[4] = {a0.x,a0.y,a0.z,a0.w}, av1[4] = {a1.x,a1.y,a1.z,a1.w};
        float bw0[4] = {b0.x,b0.y,b0.z,b0.w}, bw1[4] = {b1.x,b1.y,b1.z,b1.w};
#pragma unroll
        for (int i = 0; i < 4; i++) {
            As[0][lc+i][lr] = av0[i]; As[0][lc+i][lr+32] = av1[i];
            Bs[0][lc+i][lr] = bw0[i]; Bs[0][lc+i][lr+32] = bw1[i];
        }
    }
    __syncthreads();

    int buf = 0;
#pragma unroll 1
    for (int kb = 0; kb < 32; kb++) {
        if (kb < 31) {
            a0 = *(const float4*)(Ap + (kb + 1) * 16);
            a1 = *(const float4*)(Ap + (size_t)32 * DD + (kb + 1) * 16);
            b0 = *(const float4*)(Wp + (kb + 1) * 16);
            b1 = *(const float4*)(Wp + (size_t)32 * DD + (kb + 1) * 16);
        }
#pragma unroll
        for (int k = 0; k < 16; k++) {
            float4 av = *(const float4*)&As[buf][k][m0];
            union { float4 v; unsigned long long u[2]; } p0, p1;
            p0.v = *(const float4*)&Bs[buf][k][n0];
            p1.v = *(const float4*)&Bs[buf][k][n0 + 4];
            unsigned long long am[4] = { dup2(av.x), dup2(av.y),
                                         dup2(av.z), dup2(av.w) };
#pragma unroll
            for (int i = 0; i < 4; i++) {
                acc[i][0] = fma2(am[i], p0.u[0], acc[i][0]);
                acc[i][1] = fma2(am[i], p0.u[1], acc[i][1]);
                acc[i][2] = fma2(am[i], p1.u[0], acc[i][2]);
                acc[i][3] = fma2(am[i], p1.u[1], acc[i][3]);
            }
        }
        if (kb < 31) {
            const int nb = buf ^ 1;
            float av0[4] = {a0.x,a0.y,a0.z,a0.w}, av1[4] = {a1.x,a1.y,a1.z,a1.w};
            float bw0[4] = {b0.x,b0.y,b0.z,b0.w}, bw1[4] = {b1.x,b1.y,b1.z,b1.w};
#pragma unroll
            for (int i = 0; i < 4; i++) {
                As[nb][lc+i][lr] = av0[i]; As[nb][lc+i][lr+32] = av1[i];
                Bs[nb][lc+i][lr] = bw0[i]; Bs[nb][lc+i][lr+32] = bw1[i];
            }
            __syncthreads();
            buf = nb;
        }
    }

#pragma unroll
    for (int i = 0; i < 4; i++) {
        union { unsigned long long u[2]; float4 v; } lo, hi;
        lo.u[0] = acc[i][0]; lo.u[1] = acc[i][1];
        hi.u[0] = acc[i][2]; hi.u[1] = acc[i][3];
        float* dst = P + (size_t)(bm + m0 + i) * DD + bn + n0;
        *(float4*)dst       = lo.v;
        *(float4*)(dst + 4) = hi.v;
    }
}

// ---------------- combine: dst = act(part[2p] + part[2p+1] + bias) ----------------
// grid (128, nprob), 256 threads; idx in float4 units (32768 per problem).
__global__ void __launch_bounds__(256)
combine_kernel(float* __restrict__ dst0, const float* __restrict__ bias0, int act0,
               float* __restrict__ dst1, const float* __restrict__ bias1, int act1)
{
    const int p = blockIdx.y;
    float* dst        = p ? dst1  : dst0;
    const float* bias = p ? bias1 : bias0;
    const int act     = p ? act1  : act0;

    const int idx = blockIdx.x * 256 + threadIdx.x;
    float4 a = ((const float4*)g_part[2*p    ])[idx];
    float4 b = ((const float4*)g_part[2*p + 1])[idx];
    float4 bi = ((const float4*)bias)[idx & 255];

    float o[4] = { a.x + b.x + bi.x, a.y + b.y + bi.y,
                   a.z + b.z + bi.z, a.w + b.w + bi.w };
    if (act == 1) {
#pragma unroll
        for (int j = 0; j < 4; j++) o[j] = fmaxf(o[j], 0.0f);
    } else if (act == 2) {
#pragma unroll
        for (int j = 0; j < 4; j++) o[j] = tanhf(o[j]);
    }
    ((float4*)dst)[idx] = make_float4(o[0], o[1], o[2], o[3]);
}

// ---------------- scores[b,l] = Wa . tanh(E[b,l,:] + hoe[b,:]) + ba ----------------
// One warp per l, contiguous float4 per lane. grid (25, 128), 256 threads.
__global__ void __launch_bounds__(256)
scores_kernel(const float* __restrict__ embed,
              const float* __restrict__ Wa, const float* __restrict__ ba)
{
    const int b    = blockIdx.y;
    const int t    = threadIdx.x;
    const int w    = t >> 5;
    const int lane = t & 31;
    const int l    = blockIdx.x * 8 + w;
    if (l >= LP1) return;

    const float* row  = (l == 0) ? (g_fre + (size_t)b * DD)
                                 : (embed + ((size_t)b * LLn + (l - 1)) * DD);
    const float* hrow = g_hoe + (size_t)b * DD;

    float acc = 0.0f;
#pragma unroll
    for (int p = 0; p < 8; p++) {
        const int d = p * 128 + lane * 4;
        float4 e = *(const float4*)(row  + d);
        float4 h = *(const float4*)(hrow + d);
        float4 v = *(const float4*)(Wa   + d);
        acc = fmaf(tanh_fast(e.x + h.x), v.x, acc);
        acc = fmaf(tanh_fast(e.y + h.y), v.y, acc);
        acc = fmaf(tanh_fast(e.z + h.z), v.z, acc);
        acc = fmaf(tanh_fast(e.w + h.w), v.w, acc);
    }
#pragma unroll
    for (int o = 16; o; o >>= 1) acc += __shfl_xor_sync(0xffffffffu, acc, o);
    if (lane == 0) g_scores[b * LP1 + l] = acc + ba[0];
}

// ---------------- fused softmax + weighted sum ----------------
// att[b,:] = PI[b,0]*fr + sum_l PI[b,l+1]*conv[b,l,:] + ho[b,:]
// grid (4 d-slices, 128 b), 256 threads (64 cols x 4 l-groups).
__global__ void __launch_bounds__(256)
wsum_kernel(const float* __restrict__ conv)
{
    const int s = blockIdx.x, b = blockIdx.y, t = threadIdx.x;
    __shared__ float  sp[LP1];
    __shared__ float  red[8];
    __shared__ float4 red4[4][64];

    // softmax (recomputed per block; 4 blocks/b, cheap)
    float v = (t < LP1) ? g_scores[b * LP1 + t] : -3.4e38f;
    float m = v;
#pragma unroll
    for (int o = 16; o; o >>= 1) m = fmaxf(m, __shfl_xor_sync(0xffffffffu, m, o));
    if ((t & 31) == 0) red[t >> 5] = m;
    __syncthreads();
    float mx = red[0];
#pragma unroll
    for (int i = 1; i < 8; i++) mx = fmaxf(mx, red[i]);
    __syncthreads();

    float e = (t < LP1) ? expf(v - mx) : 0.0f;
    float su = e;
#pragma unroll
    for (int o = 16; o; o >>= 1) su += __shfl_xor_sync(0xffffffffu, su, o);
    if ((t & 31) == 0) red[t >> 5] = su;
    __syncthreads();
    float tot = red[0] + red[1] + red[2] + red[3]
              + red[4] + red[5] + red[6] + red[7];
    if (t < LP1) sp[t] = e / tot;
    __syncthreads();

    const int c  = t & 63;
    const int lg = t >> 6;
    const int d0 = (s << 8) + (c << 2);
    const float* base = conv + (size_t)b * LLn * DD + d0;

    float4 acc = make_float4(0.f, 0.f, 0.f, 0.f);
    const int l0 = lg * 49;
#pragma unroll 1
    for (int u = 0; u < 12; u++) {
        const int l = l0 + (u << 2);
        float4 v0 = *(const float4*)(base + (size_t)(l + 0) * DD);
        float4 v1 = *(const float4*)(base + (size_t)(l + 1) * DD);
        float4 v2 = *(const float4*)(base + (size_t)(l + 2) * DD);
        float4 v3 = *(const float4*)(base + (size_t)(l + 3) * DD);
        float w0 = sp[l + 1], w1 = sp[l + 2], w2 = sp[l + 3], w3 = sp[l + 4];
        acc.x += v0.x*w0 + v1.x*w1 + v2.x*w2 + v3.x*w3;
        acc.y += v0.y*w0 + v1.y*w1 + v2.y*w2 + v3.y*w3;
        acc.z += v0.z*w0 + v1.z*w1 + v2.z*w2 + v3.z*w3;
        acc.w += v0.w*w0 + v1.w*w1 + v2.w*w2 + v3.w*w3;
    }
    {   // 49th element of this group
        const int l = l0 + 48;
        float4 v0 = *(const float4*)(base + (size_t)l * DD);
        float w0 = sp[l + 1];
        acc.x += v0.x*w0; acc.y += v0.y*w0; acc.z += v0.z*w0; acc.w += v0.w*w0;
    }
    red4[lg][c] = acc;
    __syncthreads();

    if (lg == 0) {
        float4 r0 = red4[0][c], r1 = red4[1][c], r2 = red4[2][c], r3 = red4[3][c];
        float4 f = *(const float4*)(g_fr + (size_t)b * DD + d0);
        float4 h = *(const float4*)(g_ho + (size_t)b * DD + d0);
        float p0 = sp[0];
        float4 o;
        o.x = r0.x + r1.x + r2.x + r3.x + f.x * p0 + h.x;
        o.y = r0.y + r1.y + r2.y + r3.y + f.y * p0 + h.y;
        o.z = r0.z + r1.z + r2.z + r3.z + f.z * p0 + h.z;
        o.w = r0.w + r1.w + r2.w + r3.w + f.w * p0 + h.w;
        *(float4*)(g_att + (size_t)b * DD + d0) = o;
    }
}

// ---------------- host launcher ----------------
extern "C" void kernel_launch(void* const* d_in, const int* in_sizes, int n_in,
                              void* d_out, int out_size)
{
    (void)in_sizes; (void)n_in; (void)out_size;
    const float* h_out = (const float*)d_in[0];
    const float* fake  = (const float*)d_in[1];
    const float* conv  = (const float*)d_in[2];
    const float* embed = (const float*)d_in[3];
    const float* W_fr  = (const float*)d_in[4];
    const float* b_fr  = (const float*)d_in[5];
    const float* W_fre = (const float*)d_in[6];
    const float* b_fre = (const float*)d_in[7];
    const float* W_ho  = (const float*)d_in[8];
    const float* b_ho  = (const float*)d_in[9];
    const float* W_hoe = (const float*)d_in[10];
    const float* b_hoe = (const float*)d_in[11];
    const float* W_a   = (const float*)d_in[12];
    const float* b_a   = (const float*)d_in[13];
    const float* W_h   = (const float*)d_in[14];
    const float* b_h   = (const float*)d_in[15];

    float *fr, *fre, *ho, *hoe, *att;
    cudaGetSymbolAddress((void**)&fr,  g_fr);
    cudaGetSymbolAddress((void**)&fre, g_fre);
    cudaGetSymbolAddress((void**)&ho,  g_ho);
    cudaGetSymbolAddress((void**)&hoe, g_hoe);
    cudaGetSymbolAddress((void**)&att, g_att);

    // stage 1: fr = relu(fake@W_fr^T + b), ho = tanh(h_out@W_ho^T + b)
    gemm_kernel<<<dim3(16, 2, 4), 128>>>(fake, W_fr, h_out, W_ho);
    combine_kernel<<<dim3(128, 2), 256>>>(fr, b_fr, 1, ho, b_ho, 2);
    // stage 2: fre = fr@W_fre^T + b, hoe = ho@W_hoe^T + b
    gemm_kernel<<<dim3(16, 2, 4), 128>>>(fr, W_fre, ho, W_hoe);
    combine_kernel<<<dim3(128, 2), 256>>>(fre, b_fre, 0, hoe, b_hoe, 0);
    // attention
    scores_kernel<<<dim3(25, BB), 256>>>(embed, W_a, b_a);
    wsum_kernel<<<dim3(4, BB), 256>>>(conv);
    // stage 3: h = tanh(att@W_h^T + b_h)
    gemm_kernel<<<dim3(16, 2, 2), 128>>>(att, W_h, att, W_h);
    combine_kernel<<<dim3(128, 1), 256>>>((float*)d_out, b_h, 2,
                                          (float*)d_out, b_h, 2);
}

// round 7
// speedup vs baseline: 2.1959x; 1.2647x over previous
#include <cuda_runtime.h>

#define DD  1024
#define BB  128
#define LLn 196
#define LP1 197

// ---------------- scratch (no allocs allowed) ----------------
__device__ float g_fr [BB*DD];
__device__ float g_fre[BB*DD];
__device__ float g_ho [BB*DD];
__device__ float g_hoe[BB*DD];
__device__ float g_att[BB*DD];
__device__ float g_scores[BB*LP1];
__device__ float g_part[8][BB*DD];   // GEMM K-split partials (2 probs x 4 ksplit)

// ---------------- helpers ----------------
__device__ __forceinline__ unsigned long long fma2(unsigned long long a,
                                                   unsigned long long b,
                                                   unsigned long long c) {
    unsigned long long r;
    asm("fma.rn.f32x2 %0, %1, %2, %3;" : "=l"(r) : "l"(a), "l"(b), "l"(c));
    return r;
}
__device__ __forceinline__ unsigned long long dup2(float x) {
    unsigned long long r;
    asm("mov.b64 %0, {%1, %1};" : "=l"(r) : "f"(x));
    return r;
}
__device__ __forceinline__ float tanh_fast(float x) {
    float y;
    asm("tanh.approx.f32 %0, %1;" : "=f"(y) : "f"(x));
    return y;
}

// ---------------- GEMM partial: P = A[:,ks] @ W[:,ks]^T ----------------
// BM=64, BN=128, BK=16, 128 threads, thread tile 8m x 8n (m-paired f32x2 acc).
// grid (8, 2, z): z = prob*4 + ksplit; K=256 per block.
__global__ void __launch_bounds__(128)
gemm_kernel(const float* __restrict__ A0, const float* __restrict__ W0,
            const float* __restrict__ A1, const float* __restrict__ W1)
{
    const int bz = blockIdx.z;
    const float* A = (bz < 4) ? A0 : A1;
    const float* W = (bz < 4) ? W0 : W1;
    const int koff = (bz & 3) << 8;           // ksplit * 256
    float* P = g_part[bz];

    __shared__ float As[2][16][72];           // 64 rows + pad (16B-aligned rows)
    __shared__ float Bs[2][16][136];          // 128 rows + pad

    const int t  = threadIdx.x;
    const int bn = blockIdx.x << 7;           // n-tile * 128
    const int bm = blockIdx.y << 6;           // m-tile * 64

    const int lrA = t >> 1, lcA = (t & 1) << 3;   // A loader: row 0..63, k 0/8
    const float* Ap = A + (size_t)(bm + lrA) * DD + koff + lcA;
    const float* Wp = W + (size_t)(bn + t) * DD + koff;   // B loader: row = t

    const int tx = t & 15, ty = t >> 4;
    const int m0 = ty << 3, n0 = tx << 3;

    unsigned long long acc[4][8];             // [m-pair][n]
#pragma unroll
    for (int i = 0; i < 4; i++)
#pragma unroll
        for (int j = 0; j < 8; j++) acc[i][j] = 0ull;

    float4 a0 = *(const float4*)Ap;
    float4 a1 = *(const float4*)(Ap + 4);
    float4 w0 = *(const float4*)Wp;
    float4 w1 = *(const float4*)(Wp + 4);
    float4 w2 = *(const float4*)(Wp + 8);
    float4 w3 = *(const float4*)(Wp + 12);

    {
        float av[8] = {a0.x,a0.y,a0.z,a0.w,a1.x,a1.y,a1.z,a1.w};
        float wv[16] = {w0.x,w0.y,w0.z,w0.w,w1.x,w1.y,w1.z,w1.w,
                        w2.x,w2.y,w2.z,w2.w,w3.x,w3.y,w3.z,w3.w};
#pragma unroll
        for (int i = 0; i < 8; i++)  As[0][lcA + i][lrA] = av[i];
#pragma unroll
        for (int i = 0; i < 16; i++) Bs[0][i][t] = wv[i];
    }
    __syncthreads();

    int buf = 0;
#pragma unroll 1
    for (int kb = 0; kb < 16; kb++) {
        if (kb < 15) {
            a0 = *(const float4*)(Ap + (kb + 1) * 16);
            a1 = *(const float4*)(Ap + (kb + 1) * 16 + 4);
            w0 = *(const float4*)(Wp + (kb + 1) * 16);
            w1 = *(const float4*)(Wp + (kb + 1) * 16 + 4);
            w2 = *(const float4*)(Wp + (kb + 1) * 16 + 8);
            w3 = *(const float4*)(Wp + (kb + 1) * 16 + 12);
        }
#pragma unroll
        for (int k = 0; k < 16; k++) {
            union { float4 v; unsigned long long u[2]; } am0, am1;
            am0.v = *(const float4*)&As[buf][k][m0];        // m-pairs (0,1),(2,3)
            am1.v = *(const float4*)&As[buf][k][m0 + 4];    // m-pairs (4,5),(6,7)
            float4 b0 = *(const float4*)&Bs[buf][k][n0];
            float4 b1 = *(const float4*)&Bs[buf][k][n0 + 4];
            unsigned long long bd[8] = {
                dup2(b0.x), dup2(b0.y), dup2(b0.z), dup2(b0.w),
                dup2(b1.x), dup2(b1.y), dup2(b1.z), dup2(b1.w) };
            unsigned long long am[4] = { am0.u[0], am0.u[1], am1.u[0], am1.u[1] };
#pragma unroll
            for (int i = 0; i < 4; i++)
#pragma unroll
                for (int j = 0; j < 8; j++)
                    acc[i][j] = fma2(am[i], bd[j], acc[i][j]);
        }
        if (kb < 15) {
            const int nb = buf ^ 1;
            float av[8] = {a0.x,a0.y,a0.z,a0.w,a1.x,a1.y,a1.z,a1.w};
            float wv[16] = {w0.x,w0.y,w0.z,w0.w,w1.x,w1.y,w1.z,w1.w,
                            w2.x,w2.y,w2.z,w2.w,w3.x,w3.y,w3.z,w3.w};
#pragma unroll
            for (int i = 0; i < 8; i++)  As[nb][lcA + i][lrA] = av[i];
#pragma unroll
            for (int i = 0; i < 16; i++) Bs[nb][i][t] = wv[i];
            __syncthreads();
            buf = nb;
        }
    }

    // epilogue: acc[i][j] holds rows (m0+2i, m0+2i+1), col n0+j
#pragma unroll
    for (int i = 0; i < 4; i++) {
        float4 lo0, lo1, hi0, hi1;
        union { unsigned long long u; float f[2]; } c;
        c.u = acc[i][0]; lo0.x = c.f[0]; hi0.x = c.f[1];
        c.u = acc[i][1]; lo0.y = c.f[0]; hi0.y = c.f[1];
        c.u = acc[i][2]; lo0.z = c.f[0]; hi0.z = c.f[1];
        c.u = acc[i][3]; lo0.w = c.f[0]; hi0.w = c.f[1];
        c.u = acc[i][4]; lo1.x = c.f[0]; hi1.x = c.f[1];
        c.u = acc[i][5]; lo1.y = c.f[0]; hi1.y = c.f[1];
        c.u = acc[i][6]; lo1.z = c.f[0]; hi1.z = c.f[1];
        c.u = acc[i][7]; lo1.w = c.f[0]; hi1.w = c.f[1];
        float* r0 = P + (size_t)(bm + m0 + 2*i)     * DD + bn + n0;
        float* r1 = P + (size_t)(bm + m0 + 2*i + 1) * DD + bn + n0;
        *(float4*)r0       = lo0;  *(float4*)(r0 + 4) = lo1;
        *(float4*)r1       = hi0;  *(float4*)(r1 + 4) = hi1;
    }
}

// ---------------- combine: dst = act(sum of 4 partials + bias) ----------------
// grid (256, nprob), 128 threads; idx in float4 units (32768 per problem).
__global__ void __launch_bounds__(128)
combine_kernel(float* __restrict__ dst0, const float* __restrict__ bias0, int act0,
               float* __restrict__ dst1, const float* __restrict__ bias1, int act1)
{
    const int p = blockIdx.y;
    float* dst        = p ? dst1  : dst0;
    const float* bias = p ? bias1 : bias0;
    const int act     = p ? act1  : act0;

    const int idx = blockIdx.x * 128 + threadIdx.x;
    float4 a = ((const float4*)g_part[4*p    ])[idx];
    float4 b = ((const float4*)g_part[4*p + 1])[idx];
    float4 cc = ((const float4*)g_part[4*p + 2])[idx];
    float4 d = ((const float4*)g_part[4*p + 3])[idx];
    float4 bi = ((const float4*)bias)[idx & 255];

    float o[4] = { (a.x + b.x) + (cc.x + d.x) + bi.x,
                   (a.y + b.y) + (cc.y + d.y) + bi.y,
                   (a.z + b.z) + (cc.z + d.z) + bi.z,
                   (a.w + b.w) + (cc.w + d.w) + bi.w };
    if (act == 1) {
#pragma unroll
        for (int j = 0; j < 4; j++) o[j] = fmaxf(o[j], 0.0f);
    } else if (act == 2) {
#pragma unroll
        for (int j = 0; j < 4; j++) o[j] = tanhf(o[j]);
    }
    ((float4*)dst)[idx] = make_float4(o[0], o[1], o[2], o[3]);
}

// ---------------- scores[b,l] = Wa . tanh(E[b,l,:] + hoe[b,:]) + ba ----------------
// One warp per l, contiguous float4 per lane. grid (25, 128), 256 threads.
__global__ void __launch_bounds__(256)
scores_kernel(const float* __restrict__ embed,
              const float* __restrict__ Wa, const float* __restrict__ ba)
{
    const int b    = blockIdx.y;
    const int t    = threadIdx.x;
    const int w    = t >> 5;
    const int lane = t & 31;
    const int l    = blockIdx.x * 8 + w;
    if (l >= LP1) return;

    const float* row  = (l == 0) ? (g_fre + (size_t)b * DD)
                                 : (embed + ((size_t)b * LLn + (l - 1)) * DD);
    const float* hrow = g_hoe + (size_t)b * DD;

    float acc = 0.0f;
#pragma unroll
    for (int p = 0; p < 8; p++) {
        const int d = p * 128 + lane * 4;
        float4 e = *(const float4*)(row  + d);
        float4 h = *(const float4*)(hrow + d);
        float4 v = *(const float4*)(Wa   + d);
        acc = fmaf(tanh_fast(e.x + h.x), v.x, acc);
        acc = fmaf(tanh_fast(e.y + h.y), v.y, acc);
        acc = fmaf(tanh_fast(e.z + h.z), v.z, acc);
        acc = fmaf(tanh_fast(e.w + h.w), v.w, acc);
    }
#pragma unroll
    for (int o = 16; o; o >>= 1) acc += __shfl_xor_sync(0xffffffffu, acc, o);
    if (lane == 0) g_scores[b * LP1 + l] = acc + ba[0];
}

// ---------------- fused softmax + weighted sum ----------------
__global__ void __launch_bounds__(256)
wsum_kernel(const float* __restrict__ conv)
{
    const int s = blockIdx.x, b = blockIdx.y, t = threadIdx.x;
    __shared__ float  sp[LP1];
    __shared__ float  red[8];
    __shared__ float4 red4[4][64];

    float v = (t < LP1) ? g_scores[b * LP1 + t] : -3.4e38f;
    float m = v;
#pragma unroll
    for (int o = 16; o; o >>= 1) m = fmaxf(m, __shfl_xor_sync(0xffffffffu, m, o));
    if ((t & 31) == 0) red[t >> 5] = m;
    __syncthreads();
    float mx = red[0];
#pragma unroll
    for (int i = 1; i < 8; i++) mx = fmaxf(mx, red[i]);
    __syncthreads();

    float e = (t < LP1) ? expf(v - mx) : 0.0f;
    float su = e;
#pragma unroll
    for (int o = 16; o; o >>= 1) su += __shfl_xor_sync(0xffffffffu, su, o);
    if ((t & 31) == 0) red[t >> 5] = su;
    __syncthreads();
    float tot = red[0] + red[1] + red[2] + red[3]
              + red[4] + red[5] + red[6] + red[7];
    if (t < LP1) sp[t] = e / tot;
    __syncthreads();

    const int c  = t & 63;
    const int lg = t >> 6;
    const int d0 = (s << 8) + (c << 2);
    const float* base = conv + (size_t)b * LLn * DD + d0;

    float4 acc = make_float4(0.f, 0.f, 0.f, 0.f);
    const int l0 = lg * 49;
#pragma unroll 1
    for (int u = 0; u < 12; u++) {
        const int l = l0 + (u << 2);
        float4 v0 = *(const float4*)(base + (size_t)(l + 0) * DD);
        float4 v1 = *(const float4*)(base + (size_t)(l + 1) * DD);
        float4 v2 = *(const float4*)(base + (size_t)(l + 2) * DD);
        float4 v3 = *(const float4*)(base + (size_t)(l + 3) * DD);
        float w0 = sp[l + 1], w1 = sp[l + 2], w2 = sp[l + 3], w3 = sp[l + 4];
        acc.x += v0.x*w0 + v1.x*w1 + v2.x*w2 + v3.x*w3;
        acc.y += v0.y*w0 + v1.y*w1 + v2.y*w2 + v3.y*w3;
        acc.z += v0.z*w0 + v1.z*w1 + v2.z*w2 + v3.z*w3;
        acc.w += v0.w*w0 + v1.w*w1 + v2.w*w2 + v3.w*w3;
    }
    {
        const int l = l0 + 48;
        float4 v0 = *(const float4*)(base + (size_t)l * DD);
        float w0 = sp[l + 1];
        acc.x += v0.x*w0; acc.y += v0.y*w0; acc.z += v0.z*w0; acc.w += v0.w*w0;
    }
    red4[lg][c] = acc;
    __syncthreads();

    if (lg == 0) {
        float4 r0 = red4[0][c], r1 = red4[1][c], r2 = red4[2][c], r3 = red4[3][c];
        float4 f = *(const float4*)(g_fr + (size_t)b * DD + d0);
        float4 h = *(const float4*)(g_ho + (size_t)b * DD + d0);
        float p0 = sp[0];
        float4 o;
        o.x = r0.x + r1.x + r2.x + r3.x + f.x * p0 + h.x;
        o.y = r0.y + r1.y + r2.y + r3.y + f.y * p0 + h.y;
        o.z = r0.z + r1.z + r2.z + r3.z + f.z * p0 + h.z;
        o.w = r0.w + r1.w + r2.w + r3.w + f.w * p0 + h.w;
        *(float4*)(g_att + (size_t)b * DD + d0) = o;
    }
}

// ---------------- host launcher ----------------
extern "C" void kernel_launch(void* const* d_in, const int* in_sizes, int n_in,
                              void* d_out, int out_size)
{
    (void)in_sizes; (void)n_in; (void)out_size;
    const float* h_out = (const float*)d_in[0];
    const float* fake  = (const float*)d_in[1];
    const float* conv  = (const float*)d_in[2];
    const float* embed = (const float*)d_in[3];
    const float* W_fr  = (const float*)d_in[4];
    const float* b_fr  = (const float*)d_in[5];
    const float* W_fre = (const float*)d_in[6];
    const float* b_fre = (const float*)d_in[7];
    const float* W_ho  = (const float*)d_in[8];
    const float* b_ho  = (const float*)d_in[9];
    const float* W_hoe = (const float*)d_in[10];
    const float* b_hoe = (const float*)d_in[11];
    const float* W_a   = (const float*)d_in[12];
    const float* b_a   = (const float*)d_in[13];
    const float* W_h   = (const float*)d_in[14];
    const float* b_h   = (const float*)d_in[15];

    float *fr, *fre, *ho, *hoe, *att;
    cudaGetSymbolAddress((void**)&fr,  g_fr);
    cudaGetSymbolAddress((void**)&fre, g_fre);
    cudaGetSymbolAddress((void**)&ho,  g_ho);
    cudaGetSymbolAddress((void**)&hoe, g_hoe);
    cudaGetSymbolAddress((void**)&att, g_att);

    // stage 1: fr = relu(fake@W_fr^T + b), ho = tanh(h_out@W_ho^T + b)
    gemm_kernel<<<dim3(8, 2, 8), 128>>>(fake, W_fr, h_out, W_ho);
    combine_kernel<<<dim3(256, 2), 128>>>(fr, b_fr, 1, ho, b_ho, 2);
    // stage 2: fre = fr@W_fre^T + b, hoe = ho@W_hoe^T + b
    gemm_kernel<<<dim3(8, 2, 8), 128>>>(fr, W_fre, ho, W_hoe);
    combine_kernel<<<dim3(256, 2), 128>>>(fre, b_fre, 0, hoe, b_hoe, 0);
    // attention
    scores_kernel<<<dim3(25, BB), 256>>>(embed, W_a, b_a);
    wsum_kernel<<<dim3(4, BB), 256>>>(conv);
    // stage 3: h = tanh(att@W_h^T + b_h)
    gemm_kernel<<<dim3(8, 2, 4), 128>>>(att, W_h, att, W_h);
    combine_kernel<<<dim3(256, 1), 128>>>((float*)d_out, b_h, 2,
                                          (float*)d_out, b_h, 2);
}